// round 1
// baseline (speedup 1.0000x reference)
#include <cuda_runtime.h>
#include <cuda_bf16.h>

#define NMAX 100000
#define NWORDS 50000
#define EMAX 500000
#define IN_DIM 256
#define OUT_DIM 128

// ---- scratch (static device globals; no allocation) ----
__device__ float    g_z[(size_t)NMAX * OUT_DIM];   // fc output z [N,128]
__device__ float    g_s1[NMAX];                    // z . a1
__device__ float    g_s2[NMAX];                    // z . a2
__device__ float    g_e[EMAX];                     // edge scores
__device__ unsigned g_mord[NWORDS];                // segment max (ordered-uint float)
__device__ float    g_denom[NWORDS];               // segment softmax denominator

// order-preserving float<->uint mapping (monotone); ord value 0 < ord(-inf)
__device__ __forceinline__ unsigned f2ord(float f) {
    unsigned u = __float_as_uint(f);
    return (u & 0x80000000u) ? ~u : (u | 0x80000000u);
}
__device__ __forceinline__ float ord2f(unsigned u) {
    return (u & 0x80000000u) ? __uint_as_float(u & 0x7FFFFFFFu)
                             : __uint_as_float(~u);
}

// ---- init segment state ----
__global__ void init_kernel() {
    int i = blockIdx.x * blockDim.x + threadIdx.x;
    if (i < NWORDS) { g_mord[i] = 0u; g_denom[i] = 0.0f; }
}

// ---- SGEMM: z[m][n] = sum_k h[m][k] * W[n][k] ----
// BM=128, BN=128(=OUT_DIM), BK=16, 256 threads, 8x8 per-thread tile
__global__ __launch_bounds__(256) void gemm_kernel(
    const float* __restrict__ A,   // h [M,256]
    const float* __restrict__ B,   // W_fc [128,256]
    int M)
{
    __shared__ float As[16][132];
    __shared__ float Bs[16][132];

    const int block_m = blockIdx.x * 128;
    const int tid = threadIdx.x;
    const int tx = tid & 15;       // col group
    const int ty = tid >> 4;       // row group

    float acc[8][8];
#pragma unroll
    for (int i = 0; i < 8; i++)
#pragma unroll
        for (int j = 0; j < 8; j++) acc[i][j] = 0.0f;

    for (int k0 = 0; k0 < IN_DIM; k0 += 16) {
        // load A tile (128 rows x 16 k) as float4, transpose into As[k][m]
#pragma unroll
        for (int it = 0; it < 2; it++) {
            int idx = tid + it * 256;        // 0..511
            int row = idx >> 2;              // 0..127
            int k4  = (idx & 3) << 2;        // 0,4,8,12
            int gm  = block_m + row;
            float4 v = make_float4(0.f, 0.f, 0.f, 0.f);
            if (gm < M) v = *(const float4*)&A[(size_t)gm * IN_DIM + k0 + k4];
            As[k4 + 0][row] = v.x; As[k4 + 1][row] = v.y;
            As[k4 + 2][row] = v.z; As[k4 + 3][row] = v.w;
        }
        // load B tile (128 n x 16 k) -> Bs[k][n]
#pragma unroll
        for (int it = 0; it < 2; it++) {
            int idx = tid + it * 256;
            int n   = idx >> 2;
            int k4  = (idx & 3) << 2;
            float4 v = *(const float4*)&B[(size_t)n * IN_DIM + k0 + k4];
            Bs[k4 + 0][n] = v.x; Bs[k4 + 1][n] = v.y;
            Bs[k4 + 2][n] = v.z; Bs[k4 + 3][n] = v.w;
        }
        __syncthreads();

#pragma unroll
        for (int k = 0; k < 16; k++) {
            float ra[8], rb[8];
#pragma unroll
            for (int i = 0; i < 8; i++) ra[i] = As[k][ty * 8 + i];
#pragma unroll
            for (int j = 0; j < 8; j++) rb[j] = Bs[k][tx * 8 + j];
#pragma unroll
            for (int i = 0; i < 8; i++)
#pragma unroll
                for (int j = 0; j < 8; j++)
                    acc[i][j] = fmaf(ra[i], rb[j], acc[i][j]);
        }
        __syncthreads();
    }

#pragma unroll
    for (int i = 0; i < 8; i++) {
        int gm = block_m + ty * 8 + i;
        if (gm < M) {
#pragma unroll
            for (int j = 0; j < 8; j += 4) {
                float4 v = make_float4(acc[i][j], acc[i][j+1], acc[i][j+2], acc[i][j+3]);
                *(float4*)&g_z[(size_t)gm * OUT_DIM + tx * 8 + j] = v;
            }
        }
    }
}

// ---- per-node attention scalars: s1 = z.a1, s2 = z.a2 (warp per row) ----
__global__ __launch_bounds__(256) void score_kernel(const float* __restrict__ Wa, int M) {
    int gw   = (blockIdx.x * blockDim.x + threadIdx.x) >> 5;
    int lane = threadIdx.x & 31;
    if (gw >= M) return;
    float4 zv = *(const float4*)&g_z[(size_t)gw * OUT_DIM + lane * 4];
    float4 a1 = *(const float4*)&Wa[lane * 4];
    float4 a2 = *(const float4*)&Wa[OUT_DIM + lane * 4];
    float s1 = zv.x*a1.x + zv.y*a1.y + zv.z*a1.z + zv.w*a1.w;
    float s2 = zv.x*a2.x + zv.y*a2.y + zv.z*a2.z + zv.w*a2.w;
#pragma unroll
    for (int o = 16; o > 0; o >>= 1) {
        s1 += __shfl_xor_sync(0xffffffffu, s1, o);
        s2 += __shfl_xor_sync(0xffffffffu, s2, o);
    }
    if (lane == 0) { g_s1[gw] = s1; g_s2[gw] = s2; }
}

// ---- edge pass 1: score + leaky relu + zero-mask + segment max ----
__global__ __launch_bounds__(256) void edge_max_kernel(
    const int* __restrict__ src, const int* __restrict__ dst, int E)
{
    int i = blockIdx.x * blockDim.x + threadIdx.x;
    if (i >= E) return;
    int s = src[i], d = dst[i];
    float e = g_s1[s] + g_s2[d];
    e = (e > 0.0f) ? e : 0.01f * e;      // leaky_relu(0.01)
    if (e == 0.0f) e = -1000.0f;         // DGL zero-mask emulation
    g_e[i] = e;
    atomicMax(&g_mord[d], f2ord(e));
}

// ---- edge pass 2: ex = exp(e-m); denom += ex; out_raw[d] += ex * z[src] ----
// warp per edge, lane handles 4 consecutive output cols
__global__ __launch_bounds__(256) void edge_scatter_kernel(
    const int* __restrict__ src, const int* __restrict__ dst,
    float* __restrict__ out, int E)
{
    int gw   = (blockIdx.x * blockDim.x + threadIdx.x) >> 5;
    int lane = threadIdx.x & 31;
    if (gw >= E) return;
    int s = src[gw], d = dst[gw];
    float m  = ord2f(g_mord[d]);
    float ex = __expf(g_e[gw] - m);
    if (lane == 0) atomicAdd(&g_denom[d], ex);
    float4 zv = *(const float4*)&g_z[(size_t)s * OUT_DIM + lane * 4];
    float4 v = make_float4(zv.x * ex, zv.y * ex, zv.z * ex, zv.w * ex);
    float* p = out + (size_t)d * OUT_DIM + lane * 4;
    asm volatile("red.global.add.v4.f32 [%0], {%1, %2, %3, %4};"
                 :: "l"(p), "f"(v.x), "f"(v.y), "f"(v.z), "f"(v.w) : "memory");
}

// ---- normalize: out /= denom (0 for empty segments) ----
__global__ __launch_bounds__(256) void normalize_kernel(float* __restrict__ out) {
    int i = blockIdx.x * blockDim.x + threadIdx.x;
    if (i >= NWORDS * OUT_DIM) return;
    float d = g_denom[i >> 7];
    float v = out[i];
    out[i] = (d > 0.0f) ? v / d : 0.0f;
}

extern "C" void kernel_launch(void* const* d_in, const int* in_sizes, int n_in,
                              void* d_out, int out_size) {
    const float* h   = (const float*)d_in[0];
    const int*   src = (const int*)d_in[1];
    const int*   dst = (const int*)d_in[2];
    const float* Wfc = (const float*)d_in[3];
    const float* Wa  = (const float*)d_in[4];
    float* out = (float*)d_out;

    int M = in_sizes[0] / IN_DIM;   // 100000
    int E = in_sizes[1];            // 500000

    cudaMemsetAsync(d_out, 0, (size_t)out_size * sizeof(float));
    init_kernel<<<(NWORDS + 255) / 256, 256>>>();
    gemm_kernel<<<(M + 127) / 128, 256>>>(h, Wfc, M);
    score_kernel<<<((M * 32) + 255) / 256, 256>>>(Wa, M);
    edge_max_kernel<<<(E + 255) / 256, 256>>>(src, dst, E);
    edge_scatter_kernel<<<((E * 32) + 255) / 256, 256>>>(src, dst, out, E);
    normalize_kernel<<<(NWORDS * OUT_DIM + 255) / 256, 256>>>(out);
}

// round 3
// speedup vs baseline: 1.3503x; 1.3503x over previous
#include <cuda_runtime.h>
#include <cuda_bf16.h>
#include <cstdint>

#define NMAX 100000
#define NWORDS 50000
#define EMAX 500000
#define IN_DIM 256
#define OUT_DIM 128

// ---- scratch (static device globals; no allocation) ----
__device__ float    g_z[(size_t)NMAX * OUT_DIM];   // fc output z [N,128]
__device__ float    g_s1[NMAX];                    // z . a1
__device__ float    g_s2[NMAX];                    // z . a2
__device__ float    g_e[EMAX];                     // edge scores
__device__ unsigned g_mord[NWORDS];                // segment max (ordered-uint float)
__device__ float    g_denom[NWORDS];               // segment softmax denominator

// order-preserving float<->uint mapping (monotone); ord value 0 < ord(-inf)
__device__ __forceinline__ unsigned f2ord(float f) {
    unsigned u = __float_as_uint(f);
    return (u & 0x80000000u) ? ~u : (u | 0x80000000u);
}
__device__ __forceinline__ float ord2f(unsigned u) {
    return (u & 0x80000000u) ? __uint_as_float(u & 0x7FFFFFFFu)
                             : __uint_as_float(~u);
}

__device__ __forceinline__ uint32_t smem_u32(const void* p) {
    uint32_t a;
    asm("{ .reg .u64 t; cvta.to.shared.u64 t, %1; cvt.u32.u64 %0, t; }" : "=r"(a) : "l"(p));
    return a;
}
__device__ __forceinline__ void ldm_x4(uint32_t* r, uint32_t addr) {
    asm volatile("ldmatrix.sync.aligned.m8n8.x4.shared.b16 {%0,%1,%2,%3}, [%4];"
                 : "=r"(r[0]), "=r"(r[1]), "=r"(r[2]), "=r"(r[3]) : "r"(addr));
}
__device__ __forceinline__ void mma_bf16(float* c, const uint32_t* a, const uint32_t* b) {
    asm volatile(
        "mma.sync.aligned.m16n8k16.row.col.f32.bf16.bf16.f32 "
        "{%0,%1,%2,%3}, {%4,%5,%6,%7}, {%8,%9}, {%0,%1,%2,%3};"
        : "+f"(c[0]), "+f"(c[1]), "+f"(c[2]), "+f"(c[3])
        : "r"(a[0]), "r"(a[1]), "r"(a[2]), "r"(a[3]), "r"(b[0]), "r"(b[1]));
}
__device__ __forceinline__ uint32_t pack2(float a, float b) {
    __nv_bfloat162 t = __floats2bfloat162_rn(a, b);
    return *reinterpret_cast<uint32_t*>(&t);
}

// tile byte offset: row pitch 64B (32 bf16), 16B chunks xor-swizzled
__device__ __forceinline__ uint32_t tile_off(uint32_t row, uint32_t chunk) {
    return row * 64u + ((chunk ^ ((row >> 1) & 3u)) << 4);
}

// ---- init segment + score state ----
__global__ void init_kernel(int M) {
    int i = blockIdx.x * blockDim.x + threadIdx.x;
    if (i < NWORDS) { g_mord[i] = 0u; g_denom[i] = 0.0f; }
    if (i < M) { g_s1[i] = 0.0f; g_s2[i] = 0.0f; }
}

// ==========================================================================
// bf16 split-GEMM via mma.sync: z = h @ W^T (3 products: hh + hl + lh)
// BM=128, BN=128, BK=32, 256 threads (8 warps: 4 along M x 2 along N).
// Epilogue fuses s1 = z.a1, s2 = z.a2 via quad-shuffle + global reduction.
// ==========================================================================
__global__ void __launch_bounds__(256)
gemm_mma(const float* __restrict__ A,   // h [M, 256]
         const float* __restrict__ B,   // W_fc [128, 256]
         const float* __restrict__ Wa,  // W_attn [256]
         int M)
{
    __shared__ __align__(128) uint8_t sAhi[128 * 64];
    __shared__ __align__(128) uint8_t sAlo[128 * 64];
    __shared__ __align__(128) uint8_t sBhi[128 * 64];
    __shared__ __align__(128) uint8_t sBlo[128 * 64];

    const int tid  = threadIdx.x;
    const int lane = tid & 31;
    const int w    = tid >> 5;
    const int wm   = w & 3;            // warp row (32 rows each)
    const int wn   = w >> 2;           // warp col (64 cols each)
    const int block_m = blockIdx.x * 128;
    int rows_valid = M - block_m; if (rows_valid > 128) rows_valid = 128;

    const uint32_t uAhi = smem_u32(sAhi), uAlo = smem_u32(sAlo);
    const uint32_t uBhi = smem_u32(sBhi), uBlo = smem_u32(sBlo);

    // per-lane ldmatrix geometry (constant across k-chunks)
    const uint32_t a_row  = wm * 32u + (lane & 15);     // + i*16
    const uint32_t a_half = (uint32_t)lane >> 4;        // k chunk +0/+1
    const uint32_t a_sw   = (a_row >> 1) & 3u;          // invariant to +16
    const uint32_t b_row  = wn * 64u + (lane & 7) + (((uint32_t)lane >> 4) << 3); // + j*16
    const uint32_t b_half = ((uint32_t)lane >> 3) & 1u;
    const uint32_t b_sw   = (b_row >> 1) & 3u;

    float acc[2][8][4];
#pragma unroll
    for (int i = 0; i < 2; i++)
#pragma unroll
        for (int j = 0; j < 8; j++)
#pragma unroll
            for (int r = 0; r < 4; r++) acc[i][j][r] = 0.0f;

    for (int kc = 0; kc < IN_DIM / 32; kc++) {
        const int k0 = kc * 32;
        // ---- load + hi/lo split convert: A and B chunks [128 x 32] ----
#pragma unroll
        for (int it = 0; it < 2; it++) {
            int idx  = tid + it * 256;        // 0..511
            int row  = idx >> 2;              // 0..127
            int ch   = idx & 3;               // 16B chunk (8 floats source)
            uint32_t doff = tile_off((uint32_t)row, (uint32_t)ch);
            // A
            float4 v0 = make_float4(0.f, 0.f, 0.f, 0.f), v1 = v0;
            if (row < rows_valid) {
                const float* p = &A[(size_t)(block_m + row) * IN_DIM + k0 + ch * 8];
                v0 = *(const float4*)p; v1 = *(const float4*)(p + 4);
            }
            {
                uint32_t h0 = pack2(v0.x, v0.y), h1 = pack2(v0.z, v0.w);
                uint32_t h2 = pack2(v1.x, v1.y), h3 = pack2(v1.z, v1.w);
                __nv_bfloat162* q;
                q = (__nv_bfloat162*)&h0;
                uint32_t l0 = pack2(v0.x - __bfloat162float(q->x), v0.y - __bfloat162float(q->y));
                q = (__nv_bfloat162*)&h1;
                uint32_t l1 = pack2(v0.z - __bfloat162float(q->x), v0.w - __bfloat162float(q->y));
                q = (__nv_bfloat162*)&h2;
                uint32_t l2 = pack2(v1.x - __bfloat162float(q->x), v1.y - __bfloat162float(q->y));
                q = (__nv_bfloat162*)&h3;
                uint32_t l3 = pack2(v1.z - __bfloat162float(q->x), v1.w - __bfloat162float(q->y));
                *(uint4*)(sAhi + doff) = make_uint4(h0, h1, h2, h3);
                *(uint4*)(sAlo + doff) = make_uint4(l0, l1, l2, l3);
            }
            // B (always valid: 128 rows)
            {
                const float* p = &B[(size_t)row * IN_DIM + k0 + ch * 8];
                float4 w0 = *(const float4*)p, w1 = *(const float4*)(p + 4);
                uint32_t h0 = pack2(w0.x, w0.y), h1 = pack2(w0.z, w0.w);
                uint32_t h2 = pack2(w1.x, w1.y), h3 = pack2(w1.z, w1.w);
                __nv_bfloat162* q;
                q = (__nv_bfloat162*)&h0;
                uint32_t l0 = pack2(w0.x - __bfloat162float(q->x), w0.y - __bfloat162float(q->y));
                q = (__nv_bfloat162*)&h1;
                uint32_t l1 = pack2(w0.z - __bfloat162float(q->x), w0.w - __bfloat162float(q->y));
                q = (__nv_bfloat162*)&h2;
                uint32_t l2 = pack2(w1.x - __bfloat162float(q->x), w1.y - __bfloat162float(q->y));
                q = (__nv_bfloat162*)&h3;
                uint32_t l3 = pack2(w1.z - __bfloat162float(q->x), w1.w - __bfloat162float(q->y));
                *(uint4*)(sBhi + doff) = make_uint4(h0, h1, h2, h3);
                *(uint4*)(sBlo + doff) = make_uint4(l0, l1, l2, l3);
            }
        }
        __syncthreads();

#pragma unroll
        for (int ks = 0; ks < 2; ks++) {
            uint32_t ahi[2][4], alo[2][4], bb[4][4];
#pragma unroll
            for (int i = 0; i < 2; i++) {
                uint32_t off = tile_off(a_row + i * 16u, 0) -
                               ((((a_row) >> 1) & 3u) << 4) ; // row*64 only
                // recompute cleanly:
                uint32_t row = a_row + i * 16u;
                uint32_t chunk = (uint32_t)(ks * 2) + a_half;
                uint32_t o = row * 64u + ((chunk ^ a_sw) << 4);
                (void)off;
                ldm_x4(ahi[i], uAhi + o);
                ldm_x4(alo[i], uAlo + o);
            }
#pragma unroll
            for (int j = 0; j < 4; j++) {
                uint32_t row = b_row + j * 16u;
                uint32_t chunk = (uint32_t)(ks * 2) + b_half;
                uint32_t o = row * 64u + ((chunk ^ b_sw) << 4);
                ldm_x4(bb[j], uBhi + o);
            }
#pragma unroll
            for (int i = 0; i < 2; i++)
#pragma unroll
                for (int jf = 0; jf < 8; jf++) {
                    mma_bf16(acc[i][jf], ahi[i], &bb[jf >> 1][(jf & 1) * 2]);
                    mma_bf16(acc[i][jf], alo[i], &bb[jf >> 1][(jf & 1) * 2]);
                }
#pragma unroll
            for (int j = 0; j < 4; j++) {
                uint32_t row = b_row + j * 16u;
                uint32_t chunk = (uint32_t)(ks * 2) + b_half;
                uint32_t o = row * 64u + ((chunk ^ b_sw) << 4);
                ldm_x4(bb[j], uBlo + o);
            }
#pragma unroll
            for (int i = 0; i < 2; i++)
#pragma unroll
                for (int jf = 0; jf < 8; jf++)
                    mma_bf16(acc[i][jf], ahi[i], &bb[jf >> 1][(jf & 1) * 2]);
        }
        __syncthreads();
    }

    // ---- epilogue: store z, fused s1/s2 ----
    float rs1[4] = {0.f, 0.f, 0.f, 0.f}, rs2[4] = {0.f, 0.f, 0.f, 0.f};
#pragma unroll
    for (int i = 0; i < 2; i++)
#pragma unroll
        for (int jf = 0; jf < 8; jf++) {
            int n0 = wn * 64 + jf * 8 + (lane & 3) * 2;
            float a1x = __ldg(&Wa[n0]),            a1y = __ldg(&Wa[n0 + 1]);
            float a2x = __ldg(&Wa[OUT_DIM + n0]),  a2y = __ldg(&Wa[OUT_DIM + n0 + 1]);
#pragma unroll
            for (int hh = 0; hh < 2; hh++) {
                float v0 = acc[i][jf][hh * 2], v1 = acc[i][jf][hh * 2 + 1];
                int m = block_m + wm * 32 + i * 16 + hh * 8 + (lane >> 2);
                if (m < M)
                    *(float2*)&g_z[(size_t)m * OUT_DIM + n0] = make_float2(v0, v1);
                rs1[i * 2 + hh] += v0 * a1x + v1 * a1y;
                rs2[i * 2 + hh] += v0 * a2x + v1 * a2y;
            }
        }
#pragma unroll
    for (int k = 0; k < 4; k++) {
        rs1[k] += __shfl_xor_sync(0xffffffffu, rs1[k], 1);
        rs1[k] += __shfl_xor_sync(0xffffffffu, rs1[k], 2);
        rs2[k] += __shfl_xor_sync(0xffffffffu, rs2[k], 1);
        rs2[k] += __shfl_xor_sync(0xffffffffu, rs2[k], 2);
    }
    if ((lane & 3) == 0) {
#pragma unroll
        for (int k = 0; k < 4; k++) {
            int m = block_m + wm * 32 + (k >> 1) * 16 + (k & 1) * 8 + (lane >> 2);
            if (m < M) {
                atomicAdd(&g_s1[m], rs1[k]);
                atomicAdd(&g_s2[m], rs2[k]);
            }
        }
    }
}

// ---- edge pass 1: score + leaky relu + zero-mask + segment max ----
__global__ __launch_bounds__(256) void edge_max_kernel(
    const int* __restrict__ src, const int* __restrict__ dst, int E)
{
    int i = blockIdx.x * blockDim.x + threadIdx.x;
    if (i >= E) return;
    int s = src[i], d = dst[i];
    float e = g_s1[s] + g_s2[d];
    e = (e > 0.0f) ? e : 0.01f * e;      // leaky_relu(0.01)
    if (e == 0.0f) e = -1000.0f;         // DGL zero-mask emulation
    g_e[i] = e;
    atomicMax(&g_mord[d], f2ord(e));
}

// ---- edge pass 2: ex = exp(e-m); denom += ex; out_raw[d] += ex * z[src] ----
__global__ __launch_bounds__(256) void edge_scatter_kernel(
    const int* __restrict__ src, const int* __restrict__ dst,
    float* __restrict__ out, int E)
{
    int gw   = (blockIdx.x * blockDim.x + threadIdx.x) >> 5;
    int lane = threadIdx.x & 31;
    if (gw >= E) return;
    int s = src[gw], d = dst[gw];
    float m  = ord2f(g_mord[d]);
    float ex = __expf(g_e[gw] - m);
    if (lane == 0) atomicAdd(&g_denom[d], ex);
    float4 zv = *(const float4*)&g_z[(size_t)s * OUT_DIM + lane * 4];
    float4 v = make_float4(zv.x * ex, zv.y * ex, zv.z * ex, zv.w * ex);
    float* p = out + (size_t)d * OUT_DIM + lane * 4;
    asm volatile("red.global.add.v4.f32 [%0], {%1, %2, %3, %4};"
                 :: "l"(p), "f"(v.x), "f"(v.y), "f"(v.z), "f"(v.w) : "memory");
}

// ---- normalize: out /= denom (0 for empty segments) ----
__global__ __launch_bounds__(256) void normalize_kernel(float* __restrict__ out) {
    int i = blockIdx.x * blockDim.x + threadIdx.x;
    if (i >= NWORDS * OUT_DIM) return;
    float d = g_denom[i >> 7];
    float v = out[i];
    out[i] = (d > 0.0f) ? v / d : 0.0f;
}

extern "C" void kernel_launch(void* const* d_in, const int* in_sizes, int n_in,
                              void* d_out, int out_size) {
    const float* h   = (const float*)d_in[0];
    const int*   src = (const int*)d_in[1];
    const int*   dst = (const int*)d_in[2];
    const float* Wfc = (const float*)d_in[3];
    const float* Wa  = (const float*)d_in[4];
    float* out = (float*)d_out;

    int M = in_sizes[0] / IN_DIM;   // 100000
    int E = in_sizes[1];            // 500000

    cudaMemsetAsync(d_out, 0, (size_t)out_size * sizeof(float));
    init_kernel<<<(NMAX + 255) / 256, 256>>>(M);
    gemm_mma<<<(M + 127) / 128, 256>>>(h, Wfc, Wa, M);
    edge_max_kernel<<<(E + 255) / 256, 256>>>(src, dst, E);
    edge_scatter_kernel<<<((E * 32) + 255) / 256, 256>>>(src, dst, out, E);
    normalize_kernel<<<(NWORDS * OUT_DIM + 255) / 256, 256>>>(out);
}

// round 4
// speedup vs baseline: 1.4097x; 1.0440x over previous
#include <cuda_runtime.h>
#include <cuda_bf16.h>
#include <cstdint>

#define NMAX 100000
#define NWORDS 50000
#define EMAX 500000
#define IN_DIM 256
#define OUT_DIM 128

// ---- scratch (static device globals; no allocation) ----
__device__ float    g_z[(size_t)NMAX * OUT_DIM];   // fc output z [N,128]
__device__ float    g_s1[NMAX];                    // z . a1
__device__ float    g_s2[NMAX];                    // z . a2
__device__ unsigned g_cnt[NWORDS];                 // per-dst edge counts
__device__ unsigned g_cnt2[NWORDS];                // scatter cursors
__device__ unsigned g_off[NWORDS + 1];             // CSR offsets
__device__ int      g_esrc[EMAX];                  // grouped edge src ids
__device__ float    g_eval[EMAX];                  // grouped edge scores

__device__ __forceinline__ uint32_t smem_u32(const void* p) {
    uint32_t a;
    asm("{ .reg .u64 t; cvta.to.shared.u64 t, %1; cvt.u32.u64 %0, t; }" : "=r"(a) : "l"(p));
    return a;
}
__device__ __forceinline__ void ldm_x4(uint32_t* r, uint32_t addr) {
    asm volatile("ldmatrix.sync.aligned.m8n8.x4.shared.b16 {%0,%1,%2,%3}, [%4];"
                 : "=r"(r[0]), "=r"(r[1]), "=r"(r[2]), "=r"(r[3]) : "r"(addr));
}
__device__ __forceinline__ void mma_bf16(float* c, const uint32_t* a, const uint32_t* b) {
    asm volatile(
        "mma.sync.aligned.m16n8k16.row.col.f32.bf16.bf16.f32 "
        "{%0,%1,%2,%3}, {%4,%5,%6,%7}, {%8,%9}, {%0,%1,%2,%3};"
        : "+f"(c[0]), "+f"(c[1]), "+f"(c[2]), "+f"(c[3])
        : "r"(a[0]), "r"(a[1]), "r"(a[2]), "r"(a[3]), "r"(b[0]), "r"(b[1]));
}
__device__ __forceinline__ uint32_t pack2(float a, float b) {
    __nv_bfloat162 t = __floats2bfloat162_rn(a, b);
    return *reinterpret_cast<uint32_t*>(&t);
}
// tile byte offset: row pitch 64B (32 bf16), 16B chunks xor-swizzled
__device__ __forceinline__ uint32_t tile_off(uint32_t row, uint32_t chunk) {
    return row * 64u + ((chunk ^ ((row >> 1) & 3u)) << 4);
}

// ---- init counters + score accumulators ----
__global__ void init_kernel(int M) {
    int i = blockIdx.x * blockDim.x + threadIdx.x;
    if (i < NWORDS) { g_cnt[i] = 0u; g_cnt2[i] = 0u; }
    if (i < M) { g_s1[i] = 0.0f; g_s2[i] = 0.0f; }
}

// ==========================================================================
// bf16 split-GEMM via mma.sync (hh + hl + lh), fused s1/s2 epilogue.
// ==========================================================================
__global__ void __launch_bounds__(256)
gemm_mma(const float* __restrict__ A, const float* __restrict__ B,
         const float* __restrict__ Wa, int M)
{
    __shared__ __align__(128) uint8_t sAhi[128 * 64];
    __shared__ __align__(128) uint8_t sAlo[128 * 64];
    __shared__ __align__(128) uint8_t sBhi[128 * 64];
    __shared__ __align__(128) uint8_t sBlo[128 * 64];

    const int tid  = threadIdx.x;
    const int lane = tid & 31;
    const int w    = tid >> 5;
    const int wm   = w & 3;
    const int wn   = w >> 2;
    const int block_m = blockIdx.x * 128;
    int rows_valid = M - block_m; if (rows_valid > 128) rows_valid = 128;

    const uint32_t uAhi = smem_u32(sAhi), uAlo = smem_u32(sAlo);
    const uint32_t uBhi = smem_u32(sBhi), uBlo = smem_u32(sBlo);

    const uint32_t a_row  = wm * 32u + (lane & 15);
    const uint32_t a_half = (uint32_t)lane >> 4;
    const uint32_t a_sw   = (a_row >> 1) & 3u;
    const uint32_t b_row  = wn * 64u + (lane & 7) + (((uint32_t)lane >> 4) << 3);
    const uint32_t b_half = ((uint32_t)lane >> 3) & 1u;
    const uint32_t b_sw   = (b_row >> 1) & 3u;

    float acc[2][8][4];
#pragma unroll
    for (int i = 0; i < 2; i++)
#pragma unroll
        for (int j = 0; j < 8; j++)
#pragma unroll
            for (int r = 0; r < 4; r++) acc[i][j][r] = 0.0f;

    for (int kc = 0; kc < IN_DIM / 32; kc++) {
        const int k0 = kc * 32;
#pragma unroll
        for (int it = 0; it < 2; it++) {
            int idx  = tid + it * 256;
            int row  = idx >> 2;
            int ch   = idx & 3;
            uint32_t doff = tile_off((uint32_t)row, (uint32_t)ch);
            float4 v0 = make_float4(0.f, 0.f, 0.f, 0.f), v1 = v0;
            if (row < rows_valid) {
                const float* p = &A[(size_t)(block_m + row) * IN_DIM + k0 + ch * 8];
                v0 = *(const float4*)p; v1 = *(const float4*)(p + 4);
            }
            {
                uint32_t h0 = pack2(v0.x, v0.y), h1 = pack2(v0.z, v0.w);
                uint32_t h2 = pack2(v1.x, v1.y), h3 = pack2(v1.z, v1.w);
                __nv_bfloat162* q;
                q = (__nv_bfloat162*)&h0;
                uint32_t l0 = pack2(v0.x - __bfloat162float(q->x), v0.y - __bfloat162float(q->y));
                q = (__nv_bfloat162*)&h1;
                uint32_t l1 = pack2(v0.z - __bfloat162float(q->x), v0.w - __bfloat162float(q->y));
                q = (__nv_bfloat162*)&h2;
                uint32_t l2 = pack2(v1.x - __bfloat162float(q->x), v1.y - __bfloat162float(q->y));
                q = (__nv_bfloat162*)&h3;
                uint32_t l3 = pack2(v1.z - __bfloat162float(q->x), v1.w - __bfloat162float(q->y));
                *(uint4*)(sAhi + doff) = make_uint4(h0, h1, h2, h3);
                *(uint4*)(sAlo + doff) = make_uint4(l0, l1, l2, l3);
            }
            {
                const float* p = &B[(size_t)row * IN_DIM + k0 + ch * 8];
                float4 w0 = *(const float4*)p, w1 = *(const float4*)(p + 4);
                uint32_t h0 = pack2(w0.x, w0.y), h1 = pack2(w0.z, w0.w);
                uint32_t h2 = pack2(w1.x, w1.y), h3 = pack2(w1.z, w1.w);
                __nv_bfloat162* q;
                q = (__nv_bfloat162*)&h0;
                uint32_t l0 = pack2(w0.x - __bfloat162float(q->x), w0.y - __bfloat162float(q->y));
                q = (__nv_bfloat162*)&h1;
                uint32_t l1 = pack2(w0.z - __bfloat162float(q->x), w0.w - __bfloat162float(q->y));
                q = (__nv_bfloat162*)&h2;
                uint32_t l2 = pack2(w1.x - __bfloat162float(q->x), w1.y - __bfloat162float(q->y));
                q = (__nv_bfloat162*)&h3;
                uint32_t l3 = pack2(w1.z - __bfloat162float(q->x), w1.w - __bfloat162float(q->y));
                *(uint4*)(sBhi + doff) = make_uint4(h0, h1, h2, h3);
                *(uint4*)(sBlo + doff) = make_uint4(l0, l1, l2, l3);
            }
        }
        __syncthreads();

#pragma unroll
        for (int ks = 0; ks < 2; ks++) {
            uint32_t ahi[2][4], alo[2][4], bb[4][4];
#pragma unroll
            for (int i = 0; i < 2; i++) {
                uint32_t row = a_row + i * 16u;
                uint32_t chunk = (uint32_t)(ks * 2) + a_half;
                uint32_t o = row * 64u + ((chunk ^ a_sw) << 4);
                ldm_x4(ahi[i], uAhi + o);
                ldm_x4(alo[i], uAlo + o);
            }
#pragma unroll
            for (int j = 0; j < 4; j++) {
                uint32_t row = b_row + j * 16u;
                uint32_t chunk = (uint32_t)(ks * 2) + b_half;
                uint32_t o = row * 64u + ((chunk ^ b_sw) << 4);
                ldm_x4(bb[j], uBhi + o);
            }
#pragma unroll
            for (int i = 0; i < 2; i++)
#pragma unroll
                for (int jf = 0; jf < 8; jf++) {
                    mma_bf16(acc[i][jf], ahi[i], &bb[jf >> 1][(jf & 1) * 2]);
                    mma_bf16(acc[i][jf], alo[i], &bb[jf >> 1][(jf & 1) * 2]);
                }
#pragma unroll
            for (int j = 0; j < 4; j++) {
                uint32_t row = b_row + j * 16u;
                uint32_t chunk = (uint32_t)(ks * 2) + b_half;
                uint32_t o = row * 64u + ((chunk ^ b_sw) << 4);
                ldm_x4(bb[j], uBlo + o);
            }
#pragma unroll
            for (int i = 0; i < 2; i++)
#pragma unroll
                for (int jf = 0; jf < 8; jf++)
                    mma_bf16(acc[i][jf], ahi[i], &bb[jf >> 1][(jf & 1) * 2]);
        }
        __syncthreads();
    }

    float rs1[4] = {0.f, 0.f, 0.f, 0.f}, rs2[4] = {0.f, 0.f, 0.f, 0.f};
#pragma unroll
    for (int i = 0; i < 2; i++)
#pragma unroll
        for (int jf = 0; jf < 8; jf++) {
            int n0 = wn * 64 + jf * 8 + (lane & 3) * 2;
            float a1x = __ldg(&Wa[n0]),            a1y = __ldg(&Wa[n0 + 1]);
            float a2x = __ldg(&Wa[OUT_DIM + n0]),  a2y = __ldg(&Wa[OUT_DIM + n0 + 1]);
#pragma unroll
            for (int hh = 0; hh < 2; hh++) {
                float v0 = acc[i][jf][hh * 2], v1 = acc[i][jf][hh * 2 + 1];
                int m = block_m + wm * 32 + i * 16 + hh * 8 + (lane >> 2);
                if (m < M)
                    *(float2*)&g_z[(size_t)m * OUT_DIM + n0] = make_float2(v0, v1);
                rs1[i * 2 + hh] += v0 * a1x + v1 * a1y;
                rs2[i * 2 + hh] += v0 * a2x + v1 * a2y;
            }
        }
#pragma unroll
    for (int k = 0; k < 4; k++) {
        rs1[k] += __shfl_xor_sync(0xffffffffu, rs1[k], 1);
        rs1[k] += __shfl_xor_sync(0xffffffffu, rs1[k], 2);
        rs2[k] += __shfl_xor_sync(0xffffffffu, rs2[k], 1);
        rs2[k] += __shfl_xor_sync(0xffffffffu, rs2[k], 2);
    }
    if ((lane & 3) == 0) {
#pragma unroll
        for (int k = 0; k < 4; k++) {
            int m = block_m + wm * 32 + (k >> 1) * 16 + (k & 1) * 8 + (lane >> 2);
            if (m < M) {
                atomicAdd(&g_s1[m], rs1[k]);
                atomicAdd(&g_s2[m], rs2[k]);
            }
        }
    }
}

// ---- histogram of dst ----
__global__ __launch_bounds__(256) void hist_kernel(const int* __restrict__ dst, int E) {
    int i = blockIdx.x * blockDim.x + threadIdx.x;
    if (i < E) atomicAdd(&g_cnt[dst[i]], 1u);
}

// ---- single-block exclusive scan over g_cnt -> g_off ----
__global__ __launch_bounds__(1024) void scan_kernel() {
    __shared__ unsigned warp_sums[32];
    __shared__ unsigned s_carry;
    const int tid = threadIdx.x, lane = tid & 31, wid = tid >> 5;
    if (tid == 0) { s_carry = 0u; g_off[0] = 0u; }
    __syncthreads();
    for (int base = 0; base < NWORDS; base += 1024) {
        int i = base + tid;
        unsigned x = (i < NWORDS) ? g_cnt[i] : 0u;
#pragma unroll
        for (int o = 1; o < 32; o <<= 1) {
            unsigned y = __shfl_up_sync(0xffffffffu, x, o);
            if (lane >= o) x += y;
        }
        if (lane == 31) warp_sums[wid] = x;
        __syncthreads();
        if (wid == 0) {
            unsigned s = warp_sums[lane];
#pragma unroll
            for (int o = 1; o < 32; o <<= 1) {
                unsigned y = __shfl_up_sync(0xffffffffu, s, o);
                if (lane >= o) s += y;
            }
            warp_sums[lane] = s;
        }
        __syncthreads();
        unsigned incl = x + (wid > 0 ? warp_sums[wid - 1] : 0u) + s_carry;
        if (i < NWORDS) g_off[i + 1] = incl;
        __syncthreads();
        if (tid == 1023) s_carry = incl;
        __syncthreads();
    }
}

// ---- build grouped edge arrays: score + leaky relu + zero-mask ----
__global__ __launch_bounds__(256) void build_kernel(
    const int* __restrict__ src, const int* __restrict__ dst, int E)
{
    int i = blockIdx.x * blockDim.x + threadIdx.x;
    if (i >= E) return;
    int s = src[i], d = dst[i];
    float e = g_s1[s] + g_s2[d];
    e = (e > 0.0f) ? e : 0.01f * e;      // leaky_relu(0.01)
    if (e == 0.0f) e = -1000.0f;         // DGL zero-mask emulation
    unsigned pos = g_off[d] + atomicAdd(&g_cnt2[d], 1u);
    g_esrc[pos] = s;
    g_eval[pos] = e;
}

// ---- aggregate: warp per dst; softmax + weighted sum, single write ----
__global__ __launch_bounds__(256) void aggregate_kernel(float* __restrict__ out) {
    int d    = (blockIdx.x * blockDim.x + threadIdx.x) >> 5;
    int lane = threadIdx.x & 31;
    if (d >= NWORDS) return;
    int b = (int)g_off[d], eend = (int)g_off[d + 1];

    // segment max (lane-parallel)
    float mx = -1e30f;
    for (int i = b + lane; i < eend; i += 32) mx = fmaxf(mx, g_eval[i]);
#pragma unroll
    for (int o = 16; o > 0; o >>= 1)
        mx = fmaxf(mx, __shfl_xor_sync(0xffffffffu, mx, o));

    float4 acc = make_float4(0.f, 0.f, 0.f, 0.f);
    float denom = 0.f;
    int i = b;
    // unroll-2 software pipeline over edges
    for (; i + 1 < eend; i += 2) {
        float e0 = g_eval[i],     e1 = g_eval[i + 1];
        int   s0 = g_esrc[i],     s1 = g_esrc[i + 1];
        float4 z0 = *(const float4*)&g_z[(size_t)s0 * OUT_DIM + lane * 4];
        float4 z1 = *(const float4*)&g_z[(size_t)s1 * OUT_DIM + lane * 4];
        float x0 = __expf(e0 - mx), x1 = __expf(e1 - mx);
        denom += x0 + x1;
        acc.x += x0 * z0.x + x1 * z1.x;
        acc.y += x0 * z0.y + x1 * z1.y;
        acc.z += x0 * z0.z + x1 * z1.z;
        acc.w += x0 * z0.w + x1 * z1.w;
    }
    if (i < eend) {
        float e0 = g_eval[i];
        int   s0 = g_esrc[i];
        float4 z0 = *(const float4*)&g_z[(size_t)s0 * OUT_DIM + lane * 4];
        float x0 = __expf(e0 - mx);
        denom += x0;
        acc.x += x0 * z0.x; acc.y += x0 * z0.y;
        acc.z += x0 * z0.z; acc.w += x0 * z0.w;
    }
    float inv = (eend > b) ? 1.0f / denom : 0.0f;
    *(float4*)&out[(size_t)d * OUT_DIM + lane * 4] =
        make_float4(acc.x * inv, acc.y * inv, acc.z * inv, acc.w * inv);
}

extern "C" void kernel_launch(void* const* d_in, const int* in_sizes, int n_in,
                              void* d_out, int out_size) {
    const float* h   = (const float*)d_in[0];
    const int*   src = (const int*)d_in[1];
    const int*   dst = (const int*)d_in[2];
    const float* Wfc = (const float*)d_in[3];
    const float* Wa  = (const float*)d_in[4];
    float* out = (float*)d_out;

    int M = in_sizes[0] / IN_DIM;   // 100000
    int E = in_sizes[1];            // 500000

    init_kernel<<<(NMAX + 255) / 256, 256>>>(M);
    gemm_mma<<<(M + 127) / 128, 256>>>(h, Wfc, Wa, M);
    hist_kernel<<<(E + 255) / 256, 256>>>(dst, E);
    scan_kernel<<<1, 1024>>>();
    build_kernel<<<(E + 255) / 256, 256>>>(src, dst, E);
    aggregate_kernel<<<((NWORDS * 32) + 255) / 256, 256>>>(out);
}